// round 6
// baseline (speedup 1.0000x reference)
#include <cuda_runtime.h>
#include <cfloat>
#include <cstdint>

// Problem constants
#define NITEMS 2
#define CCH 64
#define HH 96
#define WW 96
#define HP 94
#define WP 94
#define MM (HP*WP)          // 8836 patches
#define KK 576              // 64 ch * 9 offsets
#define MPAD 8960           // 70 * 128
#define BM 128
#define BN 128
#define BK 16
#define NKC (KK/BK)         // 36 k-chunks
#define MT (MPAD/BM)        // 70 m-tiles
#define NTILES (MPAD/BN)    // 70 n-tiles
#define RS 20               // smem row stride in float2 (16 data + 4 pad) -> conflict-free
#define ATILE (BM*RS)       // 2560 float2 per tile buffer

// Static device scratch (allocation-free rule; .bss zero-init covers pad rows)
__device__ float g_featn[2][NITEMS][HH*WW*CCH];                     // [tensor][item][pixel][c], fp32 unit vectors
__device__ __align__(16) float2 g_Pin [NITEMS][(size_t)MPAD*KK];    // (tf32_hi, tf32_lo) input patches
__device__ __align__(16) float2 g_Pref[NITEMS][(size_t)MPAD*KK];    // (tf32_hi, tf32_lo) ref patches
__device__ int g_best[NITEMS][MM];

__device__ __forceinline__ unsigned su(const void* p) {
    return (unsigned)__cvta_generic_to_shared(p);
}

__device__ __forceinline__ uint32_t to_tf32(float a) {
    uint32_t u;
    asm("cvt.rna.tf32.f32 %0, %1;" : "=r"(u) : "f"(a));
    return u;
}

__device__ __forceinline__ void mma8(float* c, const uint32_t* a, const uint32_t* b) {
    asm volatile(
        "mma.sync.aligned.m16n8k8.row.col.f32.tf32.tf32.f32 "
        "{%0,%1,%2,%3}, {%4,%5,%6,%7}, {%8,%9}, {%0,%1,%2,%3};\n"
        : "+f"(c[0]), "+f"(c[1]), "+f"(c[2]), "+f"(c[3])
        : "r"(a[0]), "r"(a[1]), "r"(a[2]), "r"(a[3]), "r"(b[0]), "r"(b[1]));
}

// ---------------------------------------------------------------------------
// Kernel 1: per-pixel channel L2 normalization, fp32 NCHW -> fp32 [pix][c]
// ---------------------------------------------------------------------------
__global__ void normalize_kernel(const float* __restrict__ f1,
                                 const float* __restrict__ f2) {
    __shared__ float tile[CCH][65];
    __shared__ float part[4][64];
    __shared__ float scale[64];

    int t = blockIdx.y;   // 0: input, 1: ref
    int n = blockIdx.z;   // item
    int p0 = blockIdx.x * 64;
    const float* src = (t == 0 ? f1 : f2) + (size_t)n * CCH * HH * WW;

    for (int j = threadIdx.x; j < CCH * 64; j += 256) {
        int c = j >> 6, p = j & 63;
        tile[c][p] = src[(size_t)c * (HH*WW) + p0 + p];
    }
    __syncthreads();

    {
        int p = threadIdx.x & 63, q = threadIdx.x >> 6;
        float ss = 0.f;
        #pragma unroll
        for (int c = 0; c < 16; c++) {
            float v = tile[q*16 + c][p];
            ss += v * v;
        }
        part[q][p] = ss;
    }
    __syncthreads();
    if (threadIdx.x < 64) {
        float s = part[0][threadIdx.x] + part[1][threadIdx.x]
                + part[2][threadIdx.x] + part[3][threadIdx.x];
        scale[threadIdx.x] = 1.0f / fmaxf(sqrtf(s), 1e-12f);
    }
    __syncthreads();

    float* dst = g_featn[t][n];
    for (int j = threadIdx.x; j < CCH * 64; j += 256) {
        int pp = j >> 6, c = j & 63;
        dst[(size_t)(p0 + pp) * CCH + c] = tile[c][pp] * scale[pp];
    }
}

// ---------------------------------------------------------------------------
// Kernel 2: build patch matrices with tf32 hi/lo split.
// Row p = (y,x): concat of 9 pixel vectors; k = off*64 + c.
// ---------------------------------------------------------------------------
__global__ void build_kernel() {
    int p = blockIdx.x;      // patch index
    int n = blockIdx.y;      // item
    int t = blockIdx.z;      // 0 -> Pin, 1 -> Pref
    int y = p / WP, x = p % WP;
    const float* src = g_featn[t][n];
    float2* dst = (t == 0 ? g_Pin[n] : g_Pref[n]) + (size_t)p * KK;
    int c = threadIdx.x;     // 64 threads
    #pragma unroll
    for (int off = 0; off < 9; off++) {
        int dy = off / 3, dx = off % 3;
        float a = src[((size_t)(y + dy) * WW + (x + dx)) * CCH + c];
        uint32_t hu = to_tf32(a);
        float hi = __uint_as_float(hu);
        uint32_t lu = to_tf32(a - hi);
        dst[off * 64 + c] = make_float2(hi, __uint_as_float(lu));
    }
}

// ---------------------------------------------------------------------------
// Kernel 3: fused 3xTF32 GEMM (A @ B^T, fp32-accurate) + running argmax.
// 256 threads (8 warps = 4M x 2N), BM=BN=128, BK=16, double-buffered cp.async.
// hi/lo interleaved float2 in smem; direct LDS fragment loads (conflict-free
// with RS=20). First-occurrence argmax semantics preserved.
// ---------------------------------------------------------------------------
__global__ __launch_bounds__(256, 1)
void gemm_argmax_kernel() {
    extern __shared__ float2 sm[];
    // layout: [A0 | B0 | A1 | B1], each ATILE float2
    __shared__ float cand_val[2][BM];
    __shared__ int   cand_col[2][BM];
    __shared__ float run_val[BM];
    __shared__ int   run_idx[BM];

    const int item = blockIdx.y;
    const int m0 = blockIdx.x * BM;
    const int tid = threadIdx.x;
    const int lane = tid & 31;
    const int warp = tid >> 5;
    const int warpM = warp & 3;    // 32 rows each
    const int warpN = warp >> 2;   // 64 cols each

    const float2* __restrict__ Ag = g_Pin[item];
    const float2* __restrict__ Bg = g_Pref[item];

    if (tid < BM) { run_val[tid] = -FLT_MAX; run_idx[tid] = 0; }

    float acc[2][8][4];
    const int rsub = lane >> 2;    // 0..7
    const int csub = lane & 3;     // 0..3

    for (int nt = 0; nt < NTILES; nt++) {
        const int n0 = nt * BN;

        #pragma unroll
        for (int mf = 0; mf < 2; mf++)
            #pragma unroll
            for (int nf = 0; nf < 8; nf++)
                #pragma unroll
                for (int q = 0; q < 4; q++) acc[mf][nf][q] = 0.f;

        int buf = 0;
        // ---- prefetch chunk 0 ----
        {
            float2* As = sm;                 // A buf0
            float2* Bs = sm + ATILE;         // B buf0
            #pragma unroll
            for (int i = 0; i < 4; i++) {
                int idx = tid + 256 * i;
                int row = idx >> 3, seg = idx & 7;
                const float2* sp = Ag + (size_t)(m0 + row) * KK + seg * 2;
                unsigned dp = su(&As[row * RS + seg * 2]);
                asm volatile("cp.async.cg.shared.global [%0], [%1], 16;\n" :: "r"(dp), "l"(sp));
            }
            #pragma unroll
            for (int i = 0; i < 4; i++) {
                int idx = tid + 256 * i;
                int row = idx >> 3, seg = idx & 7;
                const float2* sp = Bg + (size_t)(n0 + row) * KK + seg * 2;
                unsigned dp = su(&Bs[row * RS + seg * 2]);
                asm volatile("cp.async.cg.shared.global [%0], [%1], 16;\n" :: "r"(dp), "l"(sp));
            }
            asm volatile("cp.async.commit_group;\n" ::: "memory");
        }

        for (int kc = 0; kc < NKC; kc++) {
            asm volatile("cp.async.wait_group 0;\n" ::: "memory");
            __syncthreads();

            if (kc + 1 < NKC) {
                int kb = (kc + 1) * BK;
                float2* As = sm + (buf ^ 1) * 2 * ATILE;
                float2* Bs = As + ATILE;
                #pragma unroll
                for (int i = 0; i < 4; i++) {
                    int idx = tid + 256 * i;
                    int row = idx >> 3, seg = idx & 7;
                    const float2* sp = Ag + (size_t)(m0 + row) * KK + kb + seg * 2;
                    unsigned dp = su(&As[row * RS + seg * 2]);
                    asm volatile("cp.async.cg.shared.global [%0], [%1], 16;\n" :: "r"(dp), "l"(sp));
                }
                #pragma unroll
                for (int i = 0; i < 4; i++) {
                    int idx = tid + 256 * i;
                    int row = idx >> 3, seg = idx & 7;
                    const float2* sp = Bg + (size_t)(n0 + row) * KK + kb + seg * 2;
                    unsigned dp = su(&Bs[row * RS + seg * 2]);
                    asm volatile("cp.async.cg.shared.global [%0], [%1], 16;\n" :: "r"(dp), "l"(sp));
                }
                asm volatile("cp.async.commit_group;\n" ::: "memory");
            }

            // ---- compute on buf: BK=16 -> two k8 steps ----
            const float2* As = sm + buf * 2 * ATILE;
            const float2* Bs = As + ATILE;
            #pragma unroll
            for (int s = 0; s < 2; s++) {
                const int c0 = s * 8 + csub;
                // A fragments (hi, lo)
                uint32_t ah[2][4], al[2][4];
                #pragma unroll
                for (int mf = 0; mf < 2; mf++) {
                    int rb = warpM * 32 + mf * 16 + rsub;
                    float2 v0 = As[rb * RS + c0];            // (g,   t)
                    float2 v1 = As[(rb + 8) * RS + c0];      // (g+8, t)
                    float2 v2 = As[rb * RS + c0 + 4];        // (g,   t+4)
                    float2 v3 = As[(rb + 8) * RS + c0 + 4];  // (g+8, t+4)
                    ah[mf][0] = __float_as_uint(v0.x); al[mf][0] = __float_as_uint(v0.y);
                    ah[mf][1] = __float_as_uint(v1.x); al[mf][1] = __float_as_uint(v1.y);
                    ah[mf][2] = __float_as_uint(v2.x); al[mf][2] = __float_as_uint(v2.y);
                    ah[mf][3] = __float_as_uint(v3.x); al[mf][3] = __float_as_uint(v3.y);
                }
                // B fragments: thread holds B[k=t(+4)][n=g] for each nf group
                uint32_t bh[8][2], bl[8][2];
                #pragma unroll
                for (int nf = 0; nf < 8; nf++) {
                    int nb = warpN * 64 + nf * 8 + rsub;
                    float2 w0 = Bs[nb * RS + c0];
                    float2 w1 = Bs[nb * RS + c0 + 4];
                    bh[nf][0] = __float_as_uint(w0.x); bl[nf][0] = __float_as_uint(w0.y);
                    bh[nf][1] = __float_as_uint(w1.x); bl[nf][1] = __float_as_uint(w1.y);
                }
                #pragma unroll
                for (int mf = 0; mf < 2; mf++)
                    #pragma unroll
                    for (int nf = 0; nf < 8; nf++) {
                        mma8(acc[mf][nf], ah[mf], bl[nf]);  // hi*lo
                        mma8(acc[mf][nf], al[mf], bh[nf]);  // lo*hi
                        mma8(acc[mf][nf], ah[mf], bh[nf]);  // hi*hi
                    }
            }
            __syncthreads();
            buf ^= 1;
        }

        // ---- per-tile argmax reduce (increasing column order => first occurrence) ----
        #pragma unroll
        for (int mf = 0; mf < 2; mf++) {
            #pragma unroll
            for (int half = 0; half < 2; half++) {
                float bv = -FLT_MAX; int bc = 0;
                #pragma unroll
                for (int nf = 0; nf < 8; nf++) {
                    #pragma unroll
                    for (int s = 0; s < 2; s++) {
                        float v = acc[mf][nf][half * 2 + s];
                        int lc = warpN * 64 + nf * 8 + csub * 2 + s;
                        if ((n0 + lc) < MM && v > bv) { bv = v; bc = lc; }
                    }
                }
                #pragma unroll
                for (int off = 1; off < 4; off <<= 1) {
                    float ov = __shfl_xor_sync(0xffffffffu, bv, off);
                    int oc = __shfl_xor_sync(0xffffffffu, bc, off);
                    if (ov > bv || (ov == bv && oc < bc)) { bv = ov; bc = oc; }
                }
                if (csub == 0) {
                    int rowb = warpM * 32 + mf * 16 + half * 8 + rsub;
                    cand_val[warpN][rowb] = bv;
                    cand_col[warpN][rowb] = bc;
                }
            }
        }
        __syncthreads();
        if (tid < BM) {
            float rv = run_val[tid]; int ridx = run_idx[tid];
            #pragma unroll
            for (int hh = 0; hh < 2; hh++) {   // warpN 0 (lower cols) first
                float cv = cand_val[hh][tid];
                if (cv > rv) { rv = cv; ridx = n0 + cand_col[hh][tid]; }
            }
            run_val[tid] = rv; run_idx[tid] = ridx;
        }
        __syncthreads();
    }

    if (tid < BM) {
        int row = m0 + tid;
        if (row < MM) g_best[item][row] = run_idx[tid];
    }
}

// ---------------------------------------------------------------------------
// Kernel 4: index -> flow -> shift -> channel reorder. out: (N, 18, H, W) f32
// ---------------------------------------------------------------------------
__global__ void epilogue_kernel(float* __restrict__ out) {
    int i = blockIdx.x * 256 + threadIdx.x;
    const int total = NITEMS * 18 * HH * WW;
    if (i >= total) return;
    int w = i % WW;
    int h = (i / WW) % HH;
    int ch = (i / (WW * HH)) % 18;
    int n = i / (WW * HH * 18);
    int s = ch >> 1, comp = ch & 1;
    int si = s / 3, sj = s % 3;
    int y = h - si, x = w - sj;
    float val = 0.f;
    if (y >= 0 && y < HP && x >= 0 && x < WP) {
        int idx = g_best[n][y * WP + x];
        val = (comp == 0) ? (float)(idx / WP - y) : (float)(idx % WP - x);
    }
    out[i] = val;
}

// ---------------------------------------------------------------------------
extern "C" void kernel_launch(void* const* d_in, const int* in_sizes, int n_in,
                              void* d_out, int out_size) {
    const float* f1 = (const float*)d_in[0];
    const float* f2 = (const float*)d_in[1];

    const int smem_bytes = 4 * ATILE * (int)sizeof(float2);   // 81920
    cudaFuncSetAttribute(gemm_argmax_kernel,
                         cudaFuncAttributeMaxDynamicSharedMemorySize, smem_bytes);

    normalize_kernel<<<dim3((HH * WW) / 64, 2, NITEMS), 256>>>(f1, f2);
    build_kernel<<<dim3(MM, NITEMS, 2), 64>>>();
    gemm_argmax_kernel<<<dim3(MT, NITEMS), 256, smem_bytes>>>();
    int total = NITEMS * 18 * HH * WW;
    epilogue_kernel<<<(total + 255) / 256, 256>>>((float*)d_out);
}

// round 7
// speedup vs baseline: 4.4095x; 4.4095x over previous
#include <cuda_runtime.h>
#include <cfloat>
#include <cstdint>
#include <cstring>

// Problem constants
#define NITEMS 2
#define CCH 64
#define HH 96
#define WW 96
#define HP 94
#define WP 94
#define MM (HP*WP)          // 8836 patches per item
#define SY 24               // patch rows per strip block
#define NSTRIP 4            // max strips per Dy
#define NDY 187             // Dy in [-93, 93]
#define VST 98              // plane row stride (floats), even
#define ROWF (CCH*WW)       // 6144 floats per row slab ([c][x])

// Static device scratch (allocation-free rule)
__device__ float g_feat[2][NITEMS][HH][CCH][WW];          // normalized, [t][n][row][c][x]
__device__ unsigned long long g_best64[NITEMS][MM];       // packed (value, ~r)

__device__ __forceinline__ unsigned su(const void* p) {
    return (unsigned)__cvta_generic_to_shared(p);
}

__device__ __forceinline__ unsigned long long packkey(float v, int r) {
    unsigned u = __float_as_uint(v);
    u = (u & 0x80000000u) ? ~u : (u | 0x80000000u);   // monotone float -> uint
    return ((unsigned long long)u << 32) | (unsigned)(~r);  // bigger key = better; tie -> smaller r
}

// ---------------------------------------------------------------------------
// Kernel 1: per-pixel channel L2 normalization, fp32 NCHW -> [row][c][x] fp32
// block = one image row; grid (96, 2 tensors, 2 items)
// ---------------------------------------------------------------------------
__global__ void normalize_kernel(const float* __restrict__ f1,
                                 const float* __restrict__ f2) {
    __shared__ float tile[CCH][WW + 1];
    __shared__ float scale[WW];
    int row = blockIdx.x, t = blockIdx.y, n = blockIdx.z;
    const float* src = (t == 0 ? f1 : f2) + (size_t)n * CCH * HH * WW + (size_t)row * WW;

    for (int j = threadIdx.x; j < CCH * WW; j += 256) {
        int c = j / WW, x = j % WW;
        tile[c][x] = src[(size_t)c * HH * WW + x];
    }
    __syncthreads();
    if (threadIdx.x < WW) {
        float ss = 0.f;
        #pragma unroll
        for (int c = 0; c < CCH; c++) { float v = tile[c][threadIdx.x]; ss += v * v; }
        scale[threadIdx.x] = 1.0f / fmaxf(sqrtf(ss), 1e-12f);
    }
    __syncthreads();
    float* dst = &g_feat[t][n][row][0][0];
    for (int j = threadIdx.x; j < CCH * WW; j += 256) {
        int c = j / WW, x = j % WW;
        dst[c * WW + x] = tile[c][x] * scale[x];
    }
}

// ---------------------------------------------------------------------------
// Kernel 2: reset argmax state (required every graph replay)
// ---------------------------------------------------------------------------
__global__ void init_kernel() {
    int i = blockIdx.x * 256 + threadIdx.x;
    if (i < NITEMS * MM) ((unsigned long long*)g_best64)[i] = 0ull;
}

// ---------------------------------------------------------------------------
// Kernel 3: displacement-decomposed correlation + argmax.
// Block = (item, Dy, y-strip). For each pixel-row pair (p, p+Dy):
//   rowdot[x][xr] = <fin(p,x), fref(p+Dy,xr)>  (96x96x64 SIMT GEMM, f32x2 FMA)
//   vertical 3-sum via running S1/S2 planes -> V plane for patch row y=p-2
//   horizontal 3-diagonal sum fused into argmax scan; atomicMax merge.
// ---------------------------------------------------------------------------
__device__ __forceinline__ void load_rows(const float* fa, const float* fb,
                                          float* da, float* db, int tid) {
    #pragma unroll
    for (int q = 0; q < 6; q++) {
        int off = (tid + 256 * q) * 4;     // float offset, 16B chunks
        unsigned dpa = su(da + off);
        asm volatile("cp.async.cg.shared.global [%0], [%1], 16;\n" :: "r"(dpa), "l"(fa + off));
        unsigned dpb = su(db + off);
        asm volatile("cp.async.cg.shared.global [%0], [%1], 16;\n" :: "r"(dpb), "l"(fb + off));
    }
    asm volatile("cp.async.commit_group;\n" ::: "memory");
}

__global__ __launch_bounds__(256, 1)
void corr_kernel() {
    extern __shared__ float sm[];
    float* smRows = sm;                    // 2 bufs x (A row + B row) = 4*ROWF
    float* S1 = sm + 4 * ROWF;             // HH*VST
    float* S2 = S1 + HH * VST;
    float* Vp = S2 + HH * VST;

    const int d = blockIdx.x >> 2;         // 0..186
    const int s = blockIdx.x & 3;
    const int Dy = d - 93;
    const int item = blockIdx.y;
    const int ylo = Dy < 0 ? -Dy : 0;
    const int yhi = HP - (Dy > 0 ? Dy : 0);
    const int y0 = ylo + s * SY;
    if (y0 >= yhi) return;
    int rows = yhi - y0; if (rows > SY) rows = SY;

    const int tid = threadIdx.x;
    // zero S1 and S2 (contiguous)
    for (int j = tid; j < 2 * HH * VST; j += 256) S1[j] = 0.f;

    const float* finBase  = &g_feat[0][item][0][0][0];
    const float* frefBase = &g_feat[1][item][0][0][0];

    // GEMM ownership: 16x16 thread grid, 6x6 tile each
    const int x0  = (tid & 15) * 6;
    const int xr0 = (tid >> 4) * 6;
    // reduce ownership
    const int xo = tid >> 4;
    const int r4 = tid & 15;

    // prefetch row-pair k=0
    load_rows(finBase + (size_t)y0 * ROWF, frefBase + (size_t)(y0 + Dy) * ROWF,
              smRows, smRows + ROWF, tid);

    __syncthreads();   // S planes zeroed before first pointwise

    for (int k = 0; k < rows + 2; k++) {
        const int buf = k & 1;
        asm volatile("cp.async.wait_group 0;\n" ::: "memory");
        __syncthreads();
        if (k + 1 < rows + 2) {
            int p = y0 + k + 1;
            load_rows(finBase + (size_t)p * ROWF, frefBase + (size_t)(p + Dy) * ROWF,
                      smRows + (buf ^ 1) * 2 * ROWF, smRows + (buf ^ 1) * 2 * ROWF + ROWF, tid);
        }

        const float* As = smRows + buf * 2 * ROWF;
        const float* Bs = As + ROWF;

        // ---- rowdot GEMM: acc[i][j] covers (x0+i, xr0+2j..2j+1), packed f32x2 ----
        unsigned long long acc[6][3];
        #pragma unroll
        for (int i = 0; i < 6; i++)
            #pragma unroll
            for (int j = 0; j < 3; j++) acc[i][j] = 0ull;

        #pragma unroll 8
        for (int c = 0; c < CCH; c++) {
            const float* ar = As + c * WW + x0;
            const float* br = Bs + c * WW + xr0;
            unsigned long long b0 = *(const unsigned long long*)(br);
            unsigned long long b1 = *(const unsigned long long*)(br + 2);
            unsigned long long b2 = *(const unsigned long long*)(br + 4);
            #pragma unroll
            for (int i = 0; i < 6; i++) {
                float a = ar[i];
                unsigned long long ap;
                asm("mov.b64 %0, {%1, %1};" : "=l"(ap) : "f"(a));
                asm("fma.rn.f32x2 %0, %1, %2, %0;" : "+l"(acc[i][0]) : "l"(ap), "l"(b0));
                asm("fma.rn.f32x2 %0, %1, %2, %0;" : "+l"(acc[i][1]) : "l"(ap), "l"(b1));
                asm("fma.rn.f32x2 %0, %1, %2, %0;" : "+l"(acc[i][2]) : "l"(ap), "l"(b2));
            }
        }

        // ---- pointwise vertical running sums (thread-private points, no sync) ----
        const bool emit = (k >= 2);
        #pragma unroll
        for (int i = 0; i < 6; i++) {
            int xx = x0 + i;
            float* s1p = S1 + xx * VST + xr0;
            float* s2p = S2 + xx * VST + xr0;
            float* vpp = Vp + xx * VST + xr0;
            #pragma unroll
            for (int j = 0; j < 3; j++) {
                float2 rd; memcpy(&rd, &acc[i][j], 8);
                float2 s1 = *(float2*)(s1p + 2 * j);
                float2 s2 = *(float2*)(s2p + 2 * j);
                if (emit)
                    *(float2*)(vpp + 2 * j) = make_float2(s2.x + rd.x, s2.y + rd.y);
                *(float2*)(s2p + 2 * j) = make_float2(s1.x + rd.x, s1.y + rd.y);
                *(float2*)(s1p + 2 * j) = rd;
            }
        }

        // ---- horizontal 3-diag sum + argmax over rx, merged via atomicMax ----
        if (emit) {
            __syncthreads();
            const int y = y0 + k - 2;
            const int ry = y + Dy;
            #pragma unroll
            for (int i = 0; i < 6; i++) {
                int xx = xo + 16 * i;
                float bv = -FLT_MAX; int brx = 0;
                if (xx < HP) {
                    #pragma unroll
                    for (int j = 0; j < 6; j++) {
                        int rx = r4 + 16 * j;
                        if (rx < HP) {
                            float v = Vp[xx * VST + rx]
                                    + Vp[(xx + 1) * VST + rx + 1]
                                    + Vp[(xx + 2) * VST + rx + 2];
                            if (v > bv) { bv = v; brx = rx; }
                        }
                    }
                }
                #pragma unroll
                for (int off = 8; off >= 1; off >>= 1) {
                    float ov = __shfl_down_sync(0xffffffffu, bv, off, 16);
                    int orx = __shfl_down_sync(0xffffffffu, brx, off, 16);
                    if (ov > bv || (ov == bv && orx < brx)) { bv = ov; brx = orx; }
                }
                if (r4 == 0 && xx < HP) {
                    atomicMax(&g_best64[item][y * WP + xx], packkey(bv, ry * WP + brx));
                }
            }
        }
    }
}

// ---------------------------------------------------------------------------
// Kernel 4: decode best index -> flow -> shift -> reorder. out (N,18,H,W) f32
// ---------------------------------------------------------------------------
__global__ void epilogue_kernel(float* __restrict__ out) {
    int i = blockIdx.x * 256 + threadIdx.x;
    const int total = NITEMS * 18 * HH * WW;
    if (i >= total) return;
    int w = i % WW;
    int h = (i / WW) % HH;
    int ch = (i / (WW * HH)) % 18;
    int n = i / (WW * HH * 18);
    int s = ch >> 1, comp = ch & 1;
    int si = s / 3, sj = s % 3;
    int y = h - si, x = w - sj;
    float val = 0.f;
    if (y >= 0 && y < HP && x >= 0 && x < WP) {
        unsigned long long key = g_best64[n][y * WP + x];
        int idx = (int)(~(unsigned)(key & 0xffffffffull));
        val = (comp == 0) ? (float)(idx / WP - y) : (float)(idx % WP - x);
    }
    out[i] = val;
}

// ---------------------------------------------------------------------------
extern "C" void kernel_launch(void* const* d_in, const int* in_sizes, int n_in,
                              void* d_out, int out_size) {
    const float* f1 = (const float*)d_in[0];
    const float* f2 = (const float*)d_in[1];

    const int smem_bytes = (4 * ROWF + 3 * HH * VST) * (int)sizeof(float);  // 211200
    cudaFuncSetAttribute(corr_kernel,
                         cudaFuncAttributeMaxDynamicSharedMemorySize, smem_bytes);

    normalize_kernel<<<dim3(HH, 2, NITEMS), 256>>>(f1, f2);
    init_kernel<<<(NITEMS * MM + 255) / 256, 256>>>();
    corr_kernel<<<dim3(NDY * NSTRIP, NITEMS), 256, smem_bytes>>>();
    int total = NITEMS * 18 * HH * WW;
    epilogue_kernel<<<(total + 255) / 256, 256>>>((float*)d_out);
}

// round 8
// speedup vs baseline: 4.8254x; 1.0943x over previous
#include <cuda_runtime.h>
#include <cfloat>
#include <cstdint>
#include <cstring>

// Problem constants
#define NITEMS 2
#define CCH 64
#define HH 96
#define WW 96
#define HP 94
#define WP 94
#define MM (HP*WP)          // 8836 patches per item
#define SY 24               // patch rows per strip block
#define NSTRIP 4            // max strips per Dy
#define NDY 187             // Dy in [-93, 93]
#define VST 98              // Vp plane row stride (floats)
#define ROWF (CCH*WW)       // 6144 floats per row slab ([c][x])
#define NTHR 512

// Static device scratch (allocation-free rule)
__device__ float g_feat[2][NITEMS][HH][CCH][WW];          // normalized, [t][n][row][c][x]
__device__ unsigned long long g_best64[NITEMS][MM];       // packed (value, ~r)

__device__ __forceinline__ unsigned su(const void* p) {
    return (unsigned)__cvta_generic_to_shared(p);
}

__device__ __forceinline__ unsigned long long packkey(float v, int r) {
    unsigned u = __float_as_uint(v);
    u = (u & 0x80000000u) ? ~u : (u | 0x80000000u);   // monotone float -> uint
    return ((unsigned long long)u << 32) | (unsigned)(~r);  // bigger = better; tie -> smaller r
}

// ---------------------------------------------------------------------------
// Kernel 1: per-pixel channel L2 normalization, fp32 NCHW -> [row][c][x] fp32
// ---------------------------------------------------------------------------
__global__ void normalize_kernel(const float* __restrict__ f1,
                                 const float* __restrict__ f2) {
    __shared__ float tile[CCH][WW + 1];
    __shared__ float scale[WW];
    int row = blockIdx.x, t = blockIdx.y, n = blockIdx.z;
    const float* src = (t == 0 ? f1 : f2) + (size_t)n * CCH * HH * WW + (size_t)row * WW;

    for (int j = threadIdx.x; j < CCH * WW; j += 256) {
        int c = j / WW, x = j % WW;
        tile[c][x] = src[(size_t)c * HH * WW + x];
    }
    __syncthreads();
    if (threadIdx.x < WW) {
        float ss = 0.f;
        #pragma unroll
        for (int c = 0; c < CCH; c++) { float v = tile[c][threadIdx.x]; ss += v * v; }
        scale[threadIdx.x] = 1.0f / fmaxf(sqrtf(ss), 1e-12f);
    }
    __syncthreads();
    float* dst = &g_feat[t][n][row][0][0];
    for (int j = threadIdx.x; j < CCH * WW; j += 256) {
        int c = j / WW, x = j % WW;
        dst[c * WW + x] = tile[c][x] * scale[x];
    }
}

// ---------------------------------------------------------------------------
// Kernel 2: reset argmax state (required every graph replay)
// ---------------------------------------------------------------------------
__global__ void init_kernel() {
    int i = blockIdx.x * 256 + threadIdx.x;
    if (i < NITEMS * MM) ((unsigned long long*)g_best64)[i] = 0ull;
}

// ---------------------------------------------------------------------------
// Kernel 3: displacement-decomposed correlation + argmax, 512 threads.
// Vertical running sums (S1/S2) live in registers (same thread owns a point
// across all rows of the strip). Only the V plane goes through smem for the
// cross-thread horizontal 3-diagonal argmax.
// ---------------------------------------------------------------------------
__device__ __forceinline__ void load_rows(const float* fa, const float* fb,
                                          float* da, float* db, int tid) {
    #pragma unroll
    for (int q = 0; q < 3; q++) {
        int off = (tid + NTHR * q) * 4;     // float offset, 16B chunks
        unsigned dpa = su(da + off);
        asm volatile("cp.async.cg.shared.global [%0], [%1], 16;\n" :: "r"(dpa), "l"(fa + off));
        unsigned dpb = su(db + off);
        asm volatile("cp.async.cg.shared.global [%0], [%1], 16;\n" :: "r"(dpb), "l"(fb + off));
    }
    asm volatile("cp.async.commit_group;\n" ::: "memory");
}

__global__ __launch_bounds__(NTHR, 1)
void corr_kernel() {
    extern __shared__ float sm[];
    float* smRows = sm;                    // 2 bufs x (A row + B row) = 4*ROWF
    float* Vp = sm + 4 * ROWF;             // 96*VST

    const int d = blockIdx.x >> 2;         // 0..186
    const int s = blockIdx.x & 3;
    const int Dy = d - 93;
    const int item = blockIdx.y;
    const int ylo = Dy < 0 ? -Dy : 0;
    const int yhi = HP - (Dy > 0 ? Dy : 0);
    const int y0 = ylo + s * SY;
    if (y0 >= yhi) return;
    int rows = yhi - y0; if (rows > SY) rows = SY;

    const int tid = threadIdx.x;
    const int lane = tid & 31;
    const int wrp = tid >> 5;              // 0..15

    const float* finBase  = &g_feat[0][item][0][0][0];
    const float* frefBase = &g_feat[1][item][0][0][0];

    // GEMM ownership: lane -> x (3 wide), warp -> xr (6 wide)
    const int x0  = lane * 3;
    const int xr0 = wrp * 6;

    // register state: acc + vertical running sums, packed f32x2 over xr pairs
    unsigned long long S1[3][3], S2[3][3];
    #pragma unroll
    for (int i = 0; i < 3; i++)
        #pragma unroll
        for (int j = 0; j < 3; j++) { S1[i][j] = 0ull; S2[i][j] = 0ull; }

    // prefetch row-pair k=0
    load_rows(finBase + (size_t)y0 * ROWF, frefBase + (size_t)(y0 + Dy) * ROWF,
              smRows, smRows + ROWF, tid);

    for (int k = 0; k < rows + 2; k++) {
        const int buf = k & 1;
        asm volatile("cp.async.wait_group 0;\n" ::: "memory");
        __syncthreads();
        if (k + 1 < rows + 2) {
            int p = y0 + k + 1;
            load_rows(finBase + (size_t)p * ROWF, frefBase + (size_t)(p + Dy) * ROWF,
                      smRows + (buf ^ 1) * 2 * ROWF, smRows + (buf ^ 1) * 2 * ROWF + ROWF, tid);
        }

        const float* As = smRows + buf * 2 * ROWF;
        const float* Bs = As + ROWF;

        // ---- rowdot GEMM: acc[i][j] covers (x0+i, xr0+2j..2j+1) ----
        unsigned long long acc[3][3];
        #pragma unroll
        for (int i = 0; i < 3; i++)
            #pragma unroll
            for (int j = 0; j < 3; j++) acc[i][j] = 0ull;

        #pragma unroll 8
        for (int c = 0; c < CCH; c++) {
            const float* ar = As + c * WW + x0;
            const float* br = Bs + c * WW + xr0;
            unsigned long long b0 = *(const unsigned long long*)(br);
            unsigned long long b1 = *(const unsigned long long*)(br + 2);
            unsigned long long b2 = *(const unsigned long long*)(br + 4);
            #pragma unroll
            for (int i = 0; i < 3; i++) {
                float a = ar[i];
                unsigned long long ap;
                asm("mov.b64 %0, {%1, %1};" : "=l"(ap) : "f"(a));
                asm("fma.rn.f32x2 %0, %1, %2, %0;" : "+l"(acc[i][0]) : "l"(ap), "l"(b0));
                asm("fma.rn.f32x2 %0, %1, %2, %0;" : "+l"(acc[i][1]) : "l"(ap), "l"(b1));
                asm("fma.rn.f32x2 %0, %1, %2, %0;" : "+l"(acc[i][2]) : "l"(ap), "l"(b2));
            }
        }

        // ---- vertical running sums in registers; V -> smem when emitting ----
        const bool emit = (k >= 2);
        #pragma unroll
        for (int i = 0; i < 3; i++) {
            float* vpp = Vp + (x0 + i) * VST + xr0;
            #pragma unroll
            for (int j = 0; j < 3; j++) {
                unsigned long long rd = acc[i][j];
                if (emit) {
                    unsigned long long v;
                    asm("add.rn.f32x2 %0, %1, %2;" : "=l"(v) : "l"(S2[i][j]), "l"(rd));
                    *(unsigned long long*)(vpp + 2 * j) = v;
                }
                asm("add.rn.f32x2 %0, %1, %2;" : "=l"(S2[i][j]) : "l"(S1[i][j]), "l"(rd));
                S1[i][j] = rd;
            }
        }

        // ---- horizontal 3-diag sum + argmax over rx, merged via atomicMax ----
        if (emit) {
            __syncthreads();
            const int y = y0 + k - 2;
            const int ry = y + Dy;
            #pragma unroll
            for (int i = 0; i < 6; i++) {
                int xx = wrp + 16 * i;
                float bv = -FLT_MAX; int brx = 0;
                if (xx < HP) {
                    const float* v0 = Vp + xx * VST;
                    const float* v1 = v0 + VST + 1;
                    const float* v2 = v1 + VST + 1;
                    #pragma unroll
                    for (int j = 0; j < 3; j++) {
                        int rx = lane + 32 * j;
                        if (rx < HP) {
                            float v = v0[rx] + v1[rx] + v2[rx];
                            if (v > bv) { bv = v; brx = rx; }
                        }
                    }
                }
                #pragma unroll
                for (int off = 16; off >= 1; off >>= 1) {
                    float ov = __shfl_down_sync(0xffffffffu, bv, off);
                    int orx = __shfl_down_sync(0xffffffffu, brx, off);
                    if (ov > bv || (ov == bv && orx < brx)) { bv = ov; brx = orx; }
                }
                if (lane == 0 && xx < HP) {
                    atomicMax(&g_best64[item][y * WP + xx], packkey(bv, ry * WP + brx));
                }
            }
        }
    }
}

// ---------------------------------------------------------------------------
// Kernel 4: decode best index -> flow -> shift -> reorder. out (N,18,H,W) f32
// ---------------------------------------------------------------------------
__global__ void epilogue_kernel(float* __restrict__ out) {
    int i = blockIdx.x * 256 + threadIdx.x;
    const int total = NITEMS * 18 * HH * WW;
    if (i >= total) return;
    int w = i % WW;
    int h = (i / WW) % HH;
    int ch = (i / (WW * HH)) % 18;
    int n = i / (WW * HH * 18);
    int s = ch >> 1, comp = ch & 1;
    int si = s / 3, sj = s % 3;
    int y = h - si, x = w - sj;
    float val = 0.f;
    if (y >= 0 && y < HP && x >= 0 && x < WP) {
        unsigned long long key = g_best64[n][y * WP + x];
        int idx = (int)(~(unsigned)(key & 0xffffffffull));
        val = (comp == 0) ? (float)(idx / WP - y) : (float)(idx % WP - x);
    }
    out[i] = val;
}

// ---------------------------------------------------------------------------
extern "C" void kernel_launch(void* const* d_in, const int* in_sizes, int n_in,
                              void* d_out, int out_size) {
    const float* f1 = (const float*)d_in[0];
    const float* f2 = (const float*)d_in[1];

    const int smem_bytes = (4 * ROWF + HH * VST) * (int)sizeof(float);  // ~136KB
    cudaFuncSetAttribute(corr_kernel,
                         cudaFuncAttributeMaxDynamicSharedMemorySize, smem_bytes);

    normalize_kernel<<<dim3(HH, 2, NITEMS), 256>>>(f1, f2);
    init_kernel<<<(NITEMS * MM + 255) / 256, 256>>>();
    corr_kernel<<<dim3(NDY * NSTRIP, NITEMS), NTHR, smem_bytes>>>();
    int total = NITEMS * 18 * HH * WW;
    epilogue_kernel<<<(total + 255) / 256, 256>>>((float*)d_out);
}